// round 5
// baseline (speedup 1.0000x reference)
#include <cuda_runtime.h>
#include <cstdint>

#define NB 8
#define NN 4096
#define NM 1024
#define ND 256

// ---------------- scratch (device globals; no runtime allocation) ----------------
static constexpr size_t OFF_WHT = 0;
static constexpr size_t OFF_WLT = OFF_WHT + (size_t)ND * ND;   // WlT then WgT contiguous (512x256)
static constexpr size_t OFF_WGT = OFF_WLT + (size_t)ND * ND;
static constexpr size_t OFF_BLG = OFF_WGT + (size_t)ND * ND;   // concat bias [bl|bg], 512
static constexpr size_t OFF_H   = OFF_BLG + 512;
static constexpr size_t OFF_L   = OFF_H  + (size_t)NB * NN * ND;  // L then G contiguous
static constexpr size_t OFF_G   = OFF_L  + (size_t)NB * NM * ND;
static constexpr size_t OFF_GT  = OFF_G  + (size_t)NB * NM * ND;
static constexpr size_t OFF_S   = OFF_GT + (size_t)NB * ND * NM;
static constexpr size_t SCRATCH_TOTAL = OFF_S + (size_t)NB * NN * NM;

__device__ float g_scratch[SCRATCH_TOTAL];

// ---------------- helpers ----------------
__device__ __forceinline__ uint32_t f2tf(float x) {
    uint32_t r;
    asm("cvt.rna.tf32.f32 %0, %1;" : "=r"(r) : "f"(x));
    return r;
}

__device__ __forceinline__ void cp16(uint32_t dst, const float* src) {
    asm volatile("cp.async.cg.shared.global [%0], [%1], 16;" :: "r"(dst), "l"(src));
}

#define MMA8(d, a, b)                                                          \
    asm volatile(                                                              \
        "mma.sync.aligned.m16n8k8.row.col.f32.tf32.tf32.f32 "                  \
        "{%0,%1,%2,%3},{%4,%5,%6,%7},{%8,%9},{%0,%1,%2,%3};\n"                 \
        : "+f"((d)[0]), "+f"((d)[1]), "+f"((d)[2]), "+f"((d)[3])               \
        : "r"((a)[0]), "r"((a)[1]), "r"((a)[2]), "r"((a)[3]),                  \
          "r"((b)[0]), "r"((b)[1]))

// ---------------- weight transpose + bias concat ----------------
__global__ void transpose_w_k(const float* __restrict__ Wh,
                              const float* __restrict__ Wl,
                              const float* __restrict__ Wg,
                              const float* __restrict__ bl,
                              const float* __restrict__ bg,
                              float* __restrict__ wht,
                              float* __restrict__ wlt,
                              float* __restrict__ wgt,
                              float* __restrict__ blg) {
    int i = blockIdx.x * blockDim.x + threadIdx.x;  // 65536 total
    int n = i >> 8, k = i & 255;
    wht[i] = Wh[k * ND + n];
    wlt[i] = Wl[k * ND + n];
    wgt[i] = Wg[k * ND + n];
    if (i < 512) blg[i] = (i < 256) ? bl[i] : bg[i - 256];
}

// ---------------- G transpose: GT[b][d][m] = G[b][m][d] ----------------
__global__ void transpose_g_k(const float* __restrict__ G, float* __restrict__ GT) {
    __shared__ float t[32][33];
    int b = blockIdx.z;
    int m0 = blockIdx.x * 32, d0 = blockIdx.y * 32;
    const float* src = G + (size_t)b * NM * ND;
    float* dst = GT + (size_t)b * ND * NM;
    int x = threadIdx.x, y = threadIdx.y;
#pragma unroll
    for (int i = 0; i < 32; i += 8) t[y + i][x] = src[(size_t)(m0 + y + i) * ND + d0 + x];
    __syncthreads();
#pragma unroll
    for (int i = 0; i < 32; i += 8) dst[(size_t)(d0 + y + i) * NM + m0 + x] = t[x][y + i];
}

// ---------------- TT GEMM, cp.async double-buffered ----------------
// C[row][col] = sum_k A[row][k] * Bsrc[col][k].
// Raw fp32 in smem; tf32 hi/lo conversion at fragment load.
// SPLIT: 3-MMA split-tf32. BIAS: +bias[col]. RESID: +R[row][col].
// SEG: cols 0..255 -> Cptr, 256..511 -> Cptr + 8192*256 (fused L/G output).
template <bool SPLIT, bool BIAS, bool RESID, bool SEG>
__global__ void __launch_bounds__(256)
gemm_tt(const float* __restrict__ Aptr, const float* __restrict__ Bptr,
        const float* __restrict__ bias, const float* __restrict__ Rptr,
        float* __restrict__ Cptr, int K, int Ncols,
        long long sA, long long sB, long long sC) {
    constexpr int BM = 128, BN = 128, BK = 32, LDSR = 36;
    constexpr int STAGE = 2 * BM * LDSR;  // floats per stage (A tile + B tile)
    extern __shared__ float smem_f[];

    int tid = threadIdx.x;
    int lane = tid & 31, wid = tid >> 5;
    int wm = wid >> 1, wn = wid & 1;     // 4x2 warp grid; warp tile 32x64
    int grp = lane >> 2, tq = lane & 3;  // mma fragment coords

    long long zb = blockIdx.z;
    const float* A = Aptr + zb * sA + (long long)blockIdx.x * BM * K;
    const float* Bm = Bptr + zb * sB + (long long)blockIdx.y * BN * K;
    uint32_t sbase = (uint32_t)__cvta_generic_to_shared(smem_f);

    float acc[2][8][4];
#pragma unroll
    for (int i = 0; i < 2; i++)
#pragma unroll
        for (int j = 0; j < 8; j++)
#pragma unroll
            for (int q = 0; q < 4; q++) acc[i][j][q] = 0.f;

    const int nk = K / BK;

    // prologue: tile 0 -> stage 0
    {
        uint32_t dA = sbase, dB = sbase + BM * LDSR * 4;
#pragma unroll
        for (int it = 0; it < 4; it++) {
            int idx = tid + it * 256;
            int rr = idx >> 3, cc = (idx & 7) * 4;
            uint32_t off = (uint32_t)(rr * LDSR + cc) * 4;
            cp16(dA + off, A + (long long)rr * K + cc);
            cp16(dB + off, Bm + (long long)rr * K + cc);
        }
        asm volatile("cp.async.commit_group;");
    }
    asm volatile("cp.async.wait_group 0;");
    __syncthreads();

    for (int t = 0; t < nk; t++) {
        int cur = t & 1;
        if (t + 1 < nk) {  // issue next tile into other stage (overlaps with MMAs below)
            int kc = (t + 1) * BK;
            uint32_t dA = sbase + (uint32_t)(1 - cur) * STAGE * 4;
            uint32_t dB = dA + BM * LDSR * 4;
#pragma unroll
            for (int it = 0; it < 4; it++) {
                int idx = tid + it * 256;
                int rr = idx >> 3, cc = (idx & 7) * 4;
                uint32_t off = (uint32_t)(rr * LDSR + cc) * 4;
                cp16(dA + off, A + (long long)rr * K + kc + cc);
                cp16(dB + off, Bm + (long long)rr * K + kc + cc);
            }
            asm volatile("cp.async.commit_group;");
        }

        const float* As = smem_f + cur * STAGE;
        const float* Bs = As + BM * LDSR;
#pragma unroll
        for (int ks = 0; ks < 4; ks++) {
            int k0 = ks * 8;
            uint32_t a[2][4], al[2][4];
#pragma unroll
            for (int i = 0; i < 2; i++) {
                int ro = (wm * 32 + i * 16 + grp) * LDSR + k0 + tq;
                float x0 = As[ro];
                float x1 = As[ro + 8 * LDSR];
                float x2 = As[ro + 4];
                float x3 = As[ro + 8 * LDSR + 4];
                a[i][0] = f2tf(x0); a[i][1] = f2tf(x1);
                a[i][2] = f2tf(x2); a[i][3] = f2tf(x3);
                if (SPLIT) {
                    al[i][0] = f2tf(x0 - __uint_as_float(a[i][0]));
                    al[i][1] = f2tf(x1 - __uint_as_float(a[i][1]));
                    al[i][2] = f2tf(x2 - __uint_as_float(a[i][2]));
                    al[i][3] = f2tf(x3 - __uint_as_float(a[i][3]));
                }
            }
#pragma unroll
            for (int j = 0; j < 8; j++) {
                int co = (wn * 64 + j * 8 + grp) * LDSR + k0 + tq;
                float y0 = Bs[co], y1 = Bs[co + 4];
                uint32_t b[2], bl2[2];
                b[0] = f2tf(y0); b[1] = f2tf(y1);
                if (SPLIT) {
                    bl2[0] = f2tf(y0 - __uint_as_float(b[0]));
                    bl2[1] = f2tf(y1 - __uint_as_float(b[1]));
                }
#pragma unroll
                for (int i = 0; i < 2; i++) {
                    if (SPLIT) {
                        MMA8(acc[i][j], al[i], b);
                        MMA8(acc[i][j], a[i], bl2);
                    }
                    MMA8(acc[i][j], a[i], b);
                }
            }
        }
        if (t + 1 < nk) asm volatile("cp.async.wait_group 0;");
        __syncthreads();
    }

    // epilogue
    int row0 = blockIdx.x * BM + wm * 32 + grp;
    int col0 = blockIdx.y * BN + wn * 64 + 2 * tq;
    float* C = Cptr + zb * sC;
    const float* R = RESID ? (Rptr + zb * sC) : nullptr;
#pragma unroll
    for (int i = 0; i < 2; i++) {
#pragma unroll
        for (int j = 0; j < 8; j++) {
            int row = row0 + i * 16;
            int col = col0 + j * 8;
            float2 v0 = make_float2(acc[i][j][0], acc[i][j][1]);
            float2 v1 = make_float2(acc[i][j][2], acc[i][j][3]);
            if (BIAS) {
                float2 bb = *(const float2*)(bias + col);
                v0.x += bb.x; v0.y += bb.y;
                v1.x += bb.x; v1.y += bb.y;
            }
            if (RESID) {
                float2 r0 = *(const float2*)(R + (long long)row * Ncols + col);
                float2 r1 = *(const float2*)(R + (long long)(row + 8) * Ncols + col);
                v0.x += r0.x; v0.y += r0.y;
                v1.x += r1.x; v1.y += r1.y;
            }
            if (SEG) {
                // cols 0..255 -> segment 0 (L), 256..511 -> segment 1 (G)
                float* cp0 = C + (long long)(col >> 8) * ((long long)NB * NM * ND)
                               + (long long)row * ND + (col & 255);
                *(float2*)cp0 = v0;
                *(float2*)(cp0 + 8LL * ND) = v1;
            } else {
                *(float2*)(C + (long long)row * Ncols + col) = v0;
                *(float2*)(C + (long long)(row + 8) * Ncols + col) = v1;
            }
        }
    }
}

// ---------------- softmax over M: one warp per row ----------------
__global__ void softmax_k(float* __restrict__ S) {
    int row = blockIdx.x * 8 + (threadIdx.x >> 5);
    int lane = threadIdx.x & 31;
    float4* p4 = (float4*)(S + (size_t)row * NM) + lane;
    float4 v[8];
    float mx = -1e30f;
#pragma unroll
    for (int t = 0; t < 8; t++) {
        v[t] = p4[t * 32];
        mx = fmaxf(mx, fmaxf(fmaxf(v[t].x, v[t].y), fmaxf(v[t].z, v[t].w)));
    }
#pragma unroll
    for (int o = 16; o > 0; o >>= 1) mx = fmaxf(mx, __shfl_xor_sync(0xffffffffu, mx, o));
    float sum = 0.f;
#pragma unroll
    for (int t = 0; t < 8; t++) {
        v[t].x = __expf(v[t].x - mx);
        v[t].y = __expf(v[t].y - mx);
        v[t].z = __expf(v[t].z - mx);
        v[t].w = __expf(v[t].w - mx);
        sum += v[t].x + v[t].y + v[t].z + v[t].w;
    }
#pragma unroll
    for (int o = 16; o > 0; o >>= 1) sum += __shfl_xor_sync(0xffffffffu, sum, o);
    float inv = 1.0f / sum;
#pragma unroll
    for (int t = 0; t < 8; t++) {
        v[t].x *= inv; v[t].y *= inv; v[t].z *= inv; v[t].w *= inv;
        p4[t * 32] = v[t];
    }
}

// ---------------- launch ----------------
extern "C" void kernel_launch(void* const* d_in, const int* in_sizes, int n_in,
                              void* d_out, int out_size) {
    const float* p  = (const float*)d_in[0];
    const float* r  = (const float*)d_in[1];
    // d_in[2] = batch ids (int64) — unused (implied by layout)
    const float* Wh = (const float*)d_in[3];
    const float* bh = (const float*)d_in[4];
    const float* Wl = (const float*)d_in[5];
    const float* bl = (const float*)d_in[6];
    const float* Wg = (const float*)d_in[7];
    const float* bg = (const float*)d_in[8];
    float* out = (float*)d_out;
    (void)in_sizes; (void)n_in; (void)out_size;

    float* s = nullptr;
    cudaGetSymbolAddress((void**)&s, g_scratch);
    float* WhT = s + OFF_WHT;
    float* WlT = s + OFF_WLT;   // WlT/WgT contiguous 512x256
    float* BLG = s + OFF_BLG;
    float* H   = s + OFF_H;
    float* L   = s + OFF_L;     // L/G contiguous
    float* G   = s + OFF_G;
    float* GT  = s + OFF_GT;
    float* S   = s + OFF_S;

    const int SMEM = 2 * 2 * 128 * 36 * 4;  // 73728: 2 stages x (A+B) tiles, raw fp32
    cudaFuncSetAttribute(gemm_tt<true, true, false, false>,
                         cudaFuncAttributeMaxDynamicSharedMemorySize, SMEM);
    cudaFuncSetAttribute(gemm_tt<true, true, false, true>,
                         cudaFuncAttributeMaxDynamicSharedMemorySize, SMEM);
    cudaFuncSetAttribute(gemm_tt<true, false, false, false>,
                         cudaFuncAttributeMaxDynamicSharedMemorySize, SMEM);
    cudaFuncSetAttribute(gemm_tt<false, false, true, false>,
                         cudaFuncAttributeMaxDynamicSharedMemorySize, SMEM);

    // 0. transpose weights -> [n][k]; concat biases
    transpose_w_k<<<256, 256>>>(Wh, Wl, Wg, bl, bg, WhT, WlT, WlT + (size_t)ND * ND, BLG);

    // 1. H = p @ Wh + bh   (split-tf32; rows = B*N)
    gemm_tt<true, true, false, false><<<dim3(NB * NN / 128, ND / 128, 1), 256, SMEM>>>(
        p, WhT, bh, nullptr, H, ND, ND, 0, 0, 0);

    // 2+3. [L | G] = r @ [Wl | Wg] + [bl | bg]   (fused, split-tf32, segmented output)
    gemm_tt<true, true, false, true><<<dim3(NB * NM / 128, 2 * ND / 128, 1), 256, SMEM>>>(
        r, WlT, BLG, nullptr, L, ND, ND, 0, 0, 0);

    // 4. GT[b][d][m]
    transpose_g_k<<<dim3(NM / 32, ND / 32, NB), dim3(32, 8)>>>(G, GT);

    // 5. scores[b][n][m] = sum_d H[b,n,d] * L[b,m,d]   (split-tf32, batched)
    gemm_tt<true, false, false, false><<<dim3(NN / 128, NM / 128, NB), 256, SMEM>>>(
        H, L, nullptr, nullptr, S, ND, NM,
        (long long)NN * ND, (long long)NM * ND, (long long)NN * NM);

    // 6. softmax over M (in place)
    softmax_k<<<NB * NN / 8, 256>>>(S);

    // 7. out = p + attn @ G   (plain tf32 post-softmax; batched)
    gemm_tt<false, false, true, false><<<dim3(NN / 128, ND / 128, NB), 256, SMEM>>>(
        S, GT, nullptr, p, out, NM, ND,
        (long long)NN * NM, (long long)ND * NM, (long long)NN * ND);
}